// round 1
// baseline (speedup 1.0000x reference)
#include <cuda_runtime.h>

// Problem constants
#define NB   2
#define NS   2048
#define ND   1024
#define NH   16
#define NDK  64
#define NM   (NB * NS)      // 4096 total rows

// Scratch (allocation-free rule: use __device__ globals)
__device__ float g_Q[NM * ND];
__device__ float g_K[NM * ND];
__device__ float g_V[NM * ND];
__device__ float g_ctx[NM * ND];

// ---------------------------------------------------------------------------
// SGEMM: C[m,n] = sum_k A[m,k] * W[n,k]   (both K-contiguous, row-major)
// Tile 128x128x8, 256 threads, 8x8 register tile per thread.
// ---------------------------------------------------------------------------
__device__ __forceinline__ void sgemm_body(const float* __restrict__ A,
                                           const float* __restrict__ W,
                                           float* __restrict__ C,
                                           int N, int K)
{
    __shared__ float As[8][128];
    __shared__ float Bs[8][128];

    const int tid  = threadIdx.x;
    const int m0   = blockIdx.y * 128;
    const int n0   = blockIdx.x * 128;
    const int rowb = (tid >> 4) << 3;   // 0..120
    const int colb = (tid & 15) << 3;   // 0..120
    const int lr   = tid >> 1;          // 0..127 (tile row for loading)
    const int lk   = (tid & 1) << 2;    // 0 or 4 (k chunk)

    const float* Ap = A + (size_t)(m0 + lr) * K + lk;
    const float* Wp = W + (size_t)(n0 + lr) * K + lk;

    float acc[8][8];
#pragma unroll
    for (int i = 0; i < 8; i++)
#pragma unroll
        for (int j = 0; j < 8; j++) acc[i][j] = 0.0f;

    for (int k0 = 0; k0 < K; k0 += 8) {
        float4 av = *(const float4*)(Ap + k0);
        float4 wv = *(const float4*)(Wp + k0);
        As[lk + 0][lr] = av.x; As[lk + 1][lr] = av.y;
        As[lk + 2][lr] = av.z; As[lk + 3][lr] = av.w;
        Bs[lk + 0][lr] = wv.x; Bs[lk + 1][lr] = wv.y;
        Bs[lk + 2][lr] = wv.z; Bs[lk + 3][lr] = wv.w;
        __syncthreads();

#pragma unroll
        for (int kk = 0; kk < 8; kk++) {
            float a[8], b[8];
            *(float4*)(a)     = *(const float4*)(&As[kk][rowb]);
            *(float4*)(a + 4) = *(const float4*)(&As[kk][rowb + 4]);
            *(float4*)(b)     = *(const float4*)(&Bs[kk][colb]);
            *(float4*)(b + 4) = *(const float4*)(&Bs[kk][colb + 4]);
#pragma unroll
            for (int i = 0; i < 8; i++)
#pragma unroll
                for (int j = 0; j < 8; j++)
                    acc[i][j] = fmaf(a[i], b[j], acc[i][j]);
        }
        __syncthreads();
    }

#pragma unroll
    for (int i = 0; i < 8; i++) {
        float* cp = C + (size_t)(m0 + rowb + i) * N + n0 + colb;
        *(float4*)(cp)     = make_float4(acc[i][0], acc[i][1], acc[i][2], acc[i][3]);
        *(float4*)(cp + 4) = make_float4(acc[i][4], acc[i][5], acc[i][6], acc[i][7]);
    }
}

__global__ void __launch_bounds__(256, 2)
qkv_kernel(const float* __restrict__ x, const float* __restrict__ Wq,
           const float* __restrict__ Wk, const float* __restrict__ Wv)
{
    const float* W = (blockIdx.z == 0) ? Wq : (blockIdx.z == 1) ? Wk : Wv;
    float* C       = (blockIdx.z == 0) ? g_Q : (blockIdx.z == 1) ? g_K : g_V;
    sgemm_body(x, W, C, ND, ND);
}

__global__ void __launch_bounds__(256, 2)
oproj_kernel(const float* __restrict__ Wo, float* __restrict__ out)
{
    sgemm_body(g_ctx, Wo, out, ND, ND);
}

// ---------------------------------------------------------------------------
// Flash attention, fp32. One block per (b, h, 64-query tile).
// 256 threads as 16x16: thread (tx,ty) owns S/P rows 4*ty..+3, cols 4*tx..+3,
// and O rows 4*ty..+3, dims 4*tx..+3.
// Smem: Qs[64][64] d-major; KP[64][68] (K d-major, then P row-major); Vs[64][68].
// Stride 68 => P reads in the PV loop are warp broadcasts (stride 64 would be
// a 32-way bank conflict since 64 % 32 == 0).
// ---------------------------------------------------------------------------
#define KPS 68

__global__ void __launch_bounds__(256, 2)
attn_kernel()
{
    extern __shared__ float sm[];
    float* Qs = sm;                   // [64][64]  Qs[d*64 + i]
    float* KP = sm + 64 * 64;         // [64][68]  Ks[d*KPS + j]  /  Ps[i*KPS + j]
    float* Vs = KP + 64 * KPS;        // [64][68]  Vs[j*KPS + d]

    const int tid = threadIdx.x;
    const int tx  = tid & 15;
    const int ty  = tid >> 4;
    const int bh  = blockIdx.y;       // 0..31
    const int b   = bh >> 4;
    const int h   = bh & 15;
    const int q0  = blockIdx.x * 64;

    const size_t base = (size_t)b * NS * ND + (size_t)h * NDK;
    const float* Qg = g_Q + base;
    const float* Kg = g_K + base;
    const float* Vg = g_V + base;

    // Load Q tile transposed (d-major) with 1/sqrt(dk) folded in
    {
        const int i     = tid & 63;
        const int dbase = (tid >> 6) << 4;  // 0,16,32,48
        const float* qp = Qg + (size_t)(q0 + i) * ND;
#pragma unroll
        for (int c = 0; c < 4; c++) {
            int d = dbase + c * 4;
            float4 v = *(const float4*)(qp + d);
            Qs[(d + 0) * 64 + i] = v.x * 0.125f;
            Qs[(d + 1) * 64 + i] = v.y * 0.125f;
            Qs[(d + 2) * 64 + i] = v.z * 0.125f;
            Qs[(d + 3) * 64 + i] = v.w * 0.125f;
        }
    }

    float m[4], l[4], o[4][4];
#pragma unroll
    for (int r = 0; r < 4; r++) {
        m[r] = -1e30f;
        l[r] = 0.0f;
#pragma unroll
        for (int c = 0; c < 4; c++) o[r][c] = 0.0f;
    }

    for (int kv0 = 0; kv0 < NS; kv0 += 64) {
        // Load K tile (transposed, d-major) and V tile (row-major)
        {
            const int j     = tid & 63;
            const int dbase = (tid >> 6) << 4;
            const float* kp = Kg + (size_t)(kv0 + j) * ND;
            const float* vp = Vg + (size_t)(kv0 + j) * ND;
#pragma unroll
            for (int c = 0; c < 4; c++) {
                int d = dbase + c * 4;
                float4 kv = *(const float4*)(kp + d);
                KP[(d + 0) * KPS + j] = kv.x;
                KP[(d + 1) * KPS + j] = kv.y;
                KP[(d + 2) * KPS + j] = kv.z;
                KP[(d + 3) * KPS + j] = kv.w;
                float4 vv = *(const float4*)(vp + d);
                *(float4*)(&Vs[j * KPS + d]) = vv;
            }
        }
        __syncthreads();

        // S tile = Q * K^T (scaled)
        float s[4][4];
#pragma unroll
        for (int r = 0; r < 4; r++)
#pragma unroll
            for (int c = 0; c < 4; c++) s[r][c] = 0.0f;

#pragma unroll 8
        for (int d = 0; d < 64; d++) {
            float4 qa = *(const float4*)(&Qs[d * 64 + 4 * ty]);
            float4 kb = *(const float4*)(&KP[d * KPS + 4 * tx]);
            float av[4] = {qa.x, qa.y, qa.z, qa.w};
            float bv[4] = {kb.x, kb.y, kb.z, kb.w};
#pragma unroll
            for (int r = 0; r < 4; r++)
#pragma unroll
                for (int c = 0; c < 4; c++)
                    s[r][c] = fmaf(av[r], bv[c], s[r][c]);
        }
        __syncthreads();   // done reading K before overwriting with P

        // Online softmax; write P into KP as [i][j]
#pragma unroll
        for (int r = 0; r < 4; r++) {
            float mx = fmaxf(fmaxf(s[r][0], s[r][1]), fmaxf(s[r][2], s[r][3]));
#pragma unroll
            for (int off = 8; off >= 1; off >>= 1)
                mx = fmaxf(mx, __shfl_xor_sync(0xffffffffu, mx, off));
            float mnew = fmaxf(m[r], mx);
            float corr = __expf(m[r] - mnew);
            float p0 = __expf(s[r][0] - mnew);
            float p1 = __expf(s[r][1] - mnew);
            float p2 = __expf(s[r][2] - mnew);
            float p3 = __expf(s[r][3] - mnew);
            float ls = (p0 + p1) + (p2 + p3);
#pragma unroll
            for (int off = 8; off >= 1; off >>= 1)
                ls += __shfl_xor_sync(0xffffffffu, ls, off);
            l[r] = l[r] * corr + ls;
            m[r] = mnew;
            o[r][0] *= corr; o[r][1] *= corr; o[r][2] *= corr; o[r][3] *= corr;
            *(float4*)(&KP[(4 * ty + r) * KPS + 4 * tx]) = make_float4(p0, p1, p2, p3);
        }
        __syncthreads();

        // O += P * V
#pragma unroll 4
        for (int j = 0; j < 64; j++) {
            float4 vv = *(const float4*)(&Vs[j * KPS + 4 * tx]);
#pragma unroll
            for (int r = 0; r < 4; r++) {
                float p = KP[(4 * ty + r) * KPS + j];
                o[r][0] = fmaf(p, vv.x, o[r][0]);
                o[r][1] = fmaf(p, vv.y, o[r][1]);
                o[r][2] = fmaf(p, vv.z, o[r][2]);
                o[r][3] = fmaf(p, vv.w, o[r][3]);
            }
        }
        __syncthreads();
    }

    // Epilogue: normalize, write ctx in [B,S,H,dk] layout (== [B,S,D] merged)
    float* Cg = g_ctx + base;
#pragma unroll
    for (int r = 0; r < 4; r++) {
        float inv = 1.0f / l[r];
        *(float4*)(Cg + (size_t)(q0 + 4 * ty + r) * ND + 4 * tx) =
            make_float4(o[r][0] * inv, o[r][1] * inv, o[r][2] * inv, o[r][3] * inv);
    }
}

// ---------------------------------------------------------------------------
extern "C" void kernel_launch(void* const* d_in, const int* in_sizes, int n_in,
                              void* d_out, int out_size)
{
    const float* x  = (const float*)d_in[0];
    const float* Wq = (const float*)d_in[1];
    const float* Wk = (const float*)d_in[2];
    const float* Wv = (const float*)d_in[3];
    const float* Wo = (const float*)d_in[4];
    float* out = (float*)d_out;

    // 51.2 KB dynamic smem for the attention kernel (> 48 KB default)
    cudaFuncSetAttribute(attn_kernel,
                         cudaFuncAttributeMaxDynamicSharedMemorySize,
                         64 * 1024);

    // QKV projections (fused over grid.z)
    qkv_kernel<<<dim3(ND / 128, NM / 128, 3), 256>>>(x, Wq, Wk, Wv);

    // Flash attention
    const int smem_bytes = (64 * 64 + 2 * 64 * KPS) * (int)sizeof(float);
    attn_kernel<<<dim3(NS / 64, NB * NH), 256, smem_bytes>>>();

    // Output projection -> d_out
    oproj_kernel<<<dim3(ND / 128, NM / 128), 256>>>(Wo, out);
}